// round 1
// baseline (speedup 1.0000x reference)
#include <cuda_runtime.h>
#include <math.h>

#define N_DT 0.01f
#define N_STEPS 100
#define N_OSC 50
#define N_PER 50
#define N_LIM 1.0471975511965976f   /* pi/3 */
#define MGL2  4.905f                /* m*g*l/2, I = 1 */

__global__ __launch_bounds__(832, 1)
void net_cpg_kernel(const float* __restrict__ x,
                    const float* __restrict__ fc1_w, const float* __restrict__ fc1_b,
                    const float* __restrict__ fc2_w, const float* __restrict__ fc2_b,
                    const float* __restrict__ fc3_w, const float* __restrict__ fc3_b,
                    const float* __restrict__ fcd_w, const float* __restrict__ fcd_b,
                    const float* __restrict__ fc4_w, const float* __restrict__ fc4_b,
                    const float* __restrict__ enc,  const float* __restrict__ osc_bias,
                    const float* __restrict__ dec,
                    float* __restrict__ out, int out_size)
{
    __shared__ float sh_h[128];
    __shared__ float sh_h2[128];
    __shared__ float sh_o[100];
    __shared__ float sh_tq[2][64];
    __shared__ float sh_direct;

    const int tid = threadIdx.x;
    const int g   = tid >> 4;    // oscillator id for tid < 800
    const int l16 = tid & 15;

    // ---- preload per-neuron constants into registers (overlaps prologue) ----
    float e0[4], e1[4], bb[4], dd0[4], dd1[4], w4[4];
    if (tid < 800) {
        #pragma unroll
        for (int k = 0; k < 4; ++k) {
            int n = l16 + 16 * k;
            if (n < N_PER) {
                int idx = g * N_PER + n;
                e0[k]  = enc[idx * 2 + 0];
                e1[k]  = enc[idx * 2 + 1];
                bb[k]  = osc_bias[idx];
                dd0[k] = dec[g * 2 * N_PER + n];
                dd1[k] = dec[g * 2 * N_PER + N_PER + n];
                w4[k]  = fc4_w[idx];
            } else {
                e0[k] = e1[k] = bb[k] = dd0[k] = dd1[k] = w4[k] = 0.f;
            }
        }
    }

    const float x0 = x[0], x1 = x[1];

    // ---- prologue: h = relu(fc1 x + b1) ----
    if (tid < 128) {
        float v = fmaf(fc1_w[tid * 2], x0, fmaf(fc1_w[tid * 2 + 1], x1, fc1_b[tid]));
        sh_h[tid] = fmaxf(v, 0.f);
    }
    __syncthreads();

    // h2 = relu(fc2 h + b2): 4 threads per row.  direct = fcd . h : warp 16.
    if (tid < 512) {
        int r = tid >> 2, sub = tid & 3;
        const float* wrow = fc2_w + r * 128 + sub * 32;
        const float* hv   = sh_h + sub * 32;
        float s = 0.f;
        #pragma unroll 8
        for (int k = 0; k < 32; ++k) s = fmaf(wrow[k], hv[k], s);
        s += __shfl_down_sync(0xffffffffu, s, 2);
        s += __shfl_down_sync(0xffffffffu, s, 1);
        if (sub == 0) sh_h2[r] = fmaxf(s + fc2_b[r], 0.f);
    } else if (tid < 544) {
        int lane = tid & 31;
        float s = 0.f;
        #pragma unroll
        for (int k = 0; k < 4; ++k) s = fmaf(fcd_w[lane + 32 * k], sh_h[lane + 32 * k], s);
        #pragma unroll
        for (int off = 16; off; off >>= 1) s += __shfl_down_sync(0xffffffffu, s, off);
        if (lane == 0) sh_direct = s + fcd_b[0];
    }
    __syncthreads();

    // o0 = fc3 h2 + b3 : 8 threads per row (100 rows, threads 0..799)
    if (tid < 800) {
        int r = tid >> 3, sub = tid & 7;
        const float* wrow = fc3_w + r * 128 + sub * 16;
        const float* hv   = sh_h2 + sub * 16;
        float s = 0.f;
        #pragma unroll
        for (int k = 0; k < 16; ++k) s = fmaf(wrow[k], hv[k], s);
        s += __shfl_down_sync(0xffffffffu, s, 4);
        s += __shfl_down_sync(0xffffffffu, s, 2);
        s += __shfl_down_sync(0xffffffffu, s, 1);
        if (sub == 0) sh_o[r] = s + fc3_b[r];
    }
    __syncthreads();

    // oscillator state lives in lane-0-of-group registers
    float s0 = 0.f, s1 = 0.f;
    if (tid < 800 && l16 == 0) { s0 = sh_o[g * 2]; s1 = sh_o[g * 2 + 1]; }

    float th = x0, om = 0.f;
    const float direct = sh_direct + fc4_b[0];

    // ---- main loop: one __syncthreads per step; torque reducer runs 1 step behind ----
    for (int s = 0; s <= N_STEPS; ++s) {
        const int buf = s & 1;
        if (tid < 800) {
            if (s < N_STEPS) {
                float o0v = __shfl_sync(0xffffffffu, s0, tid & 16);
                float o1v = __shfl_sync(0xffffffffu, s1, tid & 16);
                float a0 = 0.f, a1 = 0.f, at = 0.f;
                #pragma unroll
                for (int k = 0; k < 4; ++k) {
                    float a = fmaxf(fmaf(e0[k], o0v, fmaf(e1[k], o1v, bb[k])), 0.f);
                    a0 = fmaf(dd0[k], a, a0);
                    a1 = fmaf(dd1[k], a, a1);
                    at = fmaf(w4[k],  a, at);
                }
                #pragma unroll
                for (int off = 8; off; off >>= 1) {
                    a0 += __shfl_down_sync(0xffffffffu, a0, off);
                    a1 += __shfl_down_sync(0xffffffffu, a1, off);
                    at += __shfl_down_sync(0xffffffffu, at, off);
                }
                if (l16 == 0) {
                    s0 = fmaf(N_DT, a0, o0v);
                    s1 = fmaf(N_DT, a1, o1v);
                    sh_tq[buf][g] = at;
                }
            }
        } else {
            // reducer warp (threads 800..831): finalize torque of step s-1
            if (s >= 1) {
                const int pb = (s - 1) & 1;
                int lane = tid & 31;
                float t = sh_tq[pb][lane];
                if (lane + 32 < N_OSC) t += sh_tq[pb][lane + 32];
                #pragma unroll
                for (int off = 16; off; off >>= 1) t += __shfl_down_sync(0xffffffffu, t, off);
                if (lane == 0) {
                    const int st = s - 1;
                    float torque = t + direct;
                    float th2 = fmaf(N_DT, om, th);
                    float om2 = fmaf(N_DT, torque - MGL2 * sinf(th), om);
                    bool hit = (th2 > N_LIM) || (th2 < -N_LIM);
                    th2 = fminf(fmaxf(th2, -N_LIM), N_LIM);
                    om2 = hit ? 0.f : om2;
                    th = th2; om = om2;
                    out[st * 2 + 0] = th2;
                    out[st * 2 + 1] = om2;
                    if (out_size >= 2 * N_STEPS + N_STEPS) out[2 * N_STEPS + st] = torque;
                }
            }
        }
        __syncthreads();
    }
}

extern "C" void kernel_launch(void* const* d_in, const int* in_sizes, int n_in,
                              void* d_out, int out_size) {
    const float* x        = (const float*)d_in[0];
    const float* fc1_w    = (const float*)d_in[1];
    const float* fc1_b    = (const float*)d_in[2];
    const float* fc2_w    = (const float*)d_in[3];
    const float* fc2_b    = (const float*)d_in[4];
    const float* fc3_w    = (const float*)d_in[5];
    const float* fc3_b    = (const float*)d_in[6];
    const float* fcd_w    = (const float*)d_in[7];
    const float* fcd_b    = (const float*)d_in[8];
    const float* fc4_w    = (const float*)d_in[9];
    const float* fc4_b    = (const float*)d_in[10];
    const float* enc      = (const float*)d_in[11];
    const float* osc_bias = (const float*)d_in[12];
    const float* dec      = (const float*)d_in[13];
    float* out = (float*)d_out;

    net_cpg_kernel<<<1, 832>>>(x, fc1_w, fc1_b, fc2_w, fc2_b, fc3_w, fc3_b,
                               fcd_w, fcd_b, fc4_w, fc4_b, enc, osc_bias, dec,
                               out, out_size);
}

// round 2
// speedup vs baseline: 2.0104x; 2.0104x over previous
#include <cuda_runtime.h>
#include <math.h>

#define C_DT    0.01f
#define C_STEPS 100
#define C_NOSC  50
#define C_NPER  50
#define C_LIM   1.0471975511965976f   /* pi/3 */
#define C_MGL2  4.905f                /* m*g*(l/2), I = 1 */
#define LPO     13                    /* neurons per lane (4 lanes/osc) */

__global__ __launch_bounds__(256, 1)
void net_cpg_kernel(const float* __restrict__ x,
                    const float* __restrict__ fc1_w, const float* __restrict__ fc1_b,
                    const float* __restrict__ fc2_w, const float* __restrict__ fc2_b,
                    const float* __restrict__ fc3_w, const float* __restrict__ fc3_b,
                    const float* __restrict__ fcd_w, const float* __restrict__ fcd_b,
                    const float* __restrict__ fc4_w, const float* __restrict__ fc4_b,
                    const float* __restrict__ enc,  const float* __restrict__ osc_bias,
                    const float* __restrict__ dec,
                    float* __restrict__ out, int out_size)
{
    __shared__ float sh_h[128];
    __shared__ float sh_h2[128];
    __shared__ float sh_o[100];
    __shared__ float sh_tq[C_STEPS][C_NOSC + 1];   // padded row -> conflict-free column reads
    __shared__ float sh_torque[C_STEPS];
    __shared__ float sh_l[2 * C_STEPS];
    __shared__ float sh_direct;

    const int tid = threadIdx.x;
    const int g   = tid >> 2;      // oscillator id (tid < 200)
    const int l4  = tid & 3;

    // ---- preload per-neuron constants into registers (overlaps prologue loads) ----
    float e0[LPO], e1[LPO], bb[LPO], d0[LPO], d1[LPO], w4[LPO];
    if (tid < 200) {
        #pragma unroll
        for (int k = 0; k < LPO; ++k) {
            int n = l4 + 4 * k;
            if (n < C_NPER) {
                int idx = g * C_NPER + n;
                e0[k] = enc[idx * 2 + 0];
                e1[k] = enc[idx * 2 + 1];
                bb[k] = osc_bias[idx];
                d0[k] = dec[g * 2 * C_NPER + n];
                d1[k] = dec[g * 2 * C_NPER + C_NPER + n];
                w4[k] = fc4_w[idx];
            } else {
                e0[k] = e1[k] = bb[k] = d0[k] = d1[k] = w4[k] = 0.f;
            }
        }
    }

    const float x0 = x[0], x1 = x[1];

    // ---- h = relu(fc1 @ x + b1) ----
    if (tid < 128) {
        float v = fmaf(fc1_w[tid * 2], x0, fmaf(fc1_w[tid * 2 + 1], x1, fc1_b[tid]));
        sh_h[tid] = fmaxf(v, 0.f);
    }
    __syncthreads();

    // ---- h2 = relu(fc2 @ h + b2): one row per thread, float4 loads, 4 accumulators.
    //      direct = fcd . h + fcd_b: warp 4 concurrently. ----
    if (tid < 128) {
        const float4* wr = (const float4*)(fc2_w + tid * 128);
        float a0 = 0.f, a1 = 0.f, a2 = 0.f, a3 = 0.f;
        #pragma unroll 8
        for (int j = 0; j < 32; ++j) {
            float4 w = wr[j];
            a0 = fmaf(w.x, sh_h[4 * j + 0], a0);
            a1 = fmaf(w.y, sh_h[4 * j + 1], a1);
            a2 = fmaf(w.z, sh_h[4 * j + 2], a2);
            a3 = fmaf(w.w, sh_h[4 * j + 3], a3);
        }
        sh_h2[tid] = fmaxf((a0 + a1) + (a2 + a3) + fc2_b[tid], 0.f);
    } else if (tid < 160) {
        int lane = tid & 31;
        float s = 0.f;
        #pragma unroll
        for (int k = 0; k < 4; ++k)
            s = fmaf(fcd_w[lane + 32 * k], sh_h[lane + 32 * k], s);
        #pragma unroll
        for (int off = 16; off; off >>= 1)
            s += __shfl_down_sync(0xffffffffu, s, off);
        if (lane == 0) sh_direct = s + fcd_b[0];
    }
    __syncthreads();

    // ---- o0 = fc3 @ h2 + b3: one of 100 rows per thread ----
    if (tid < 100) {
        const float4* wr = (const float4*)(fc3_w + tid * 128);
        float a0 = 0.f, a1 = 0.f, a2 = 0.f, a3 = 0.f;
        #pragma unroll 8
        for (int j = 0; j < 32; ++j) {
            float4 w = wr[j];
            a0 = fmaf(w.x, sh_h2[4 * j + 0], a0);
            a1 = fmaf(w.y, sh_h2[4 * j + 1], a1);
            a2 = fmaf(w.z, sh_h2[4 * j + 2], a2);
            a3 = fmaf(w.w, sh_h2[4 * j + 3], a3);
        }
        sh_o[tid] = (a0 + a1) + (a2 + a3) + fc3_b[tid];
    }
    __syncthreads();

    // ---- main recurrence: NO barriers. Each 4-lane group is independent.
    //      Butterfly reduce makes all 4 lanes hold identical state. ----
    if (tid < 200) {
        const unsigned amask = __activemask();   // converged here; full warps or lanes 0..7 of warp 6
        float s0 = sh_o[2 * g];
        float s1 = sh_o[2 * g + 1];

        for (int s = 0; s < C_STEPS; ++s) {
            float a0 = 0.f, a1 = 0.f, at = 0.f;
            #pragma unroll
            for (int k = 0; k < LPO; ++k) {
                float a = fmaxf(fmaf(e0[k], s0, fmaf(e1[k], s1, bb[k])), 0.f);
                a0 = fmaf(d0[k], a, a0);
                a1 = fmaf(d1[k], a, a1);
                at = fmaf(w4[k], a, at);
            }
            // 2-level butterfly over the 4-lane group (width = 4)
            a0 += __shfl_xor_sync(amask, a0, 1, 4);
            a1 += __shfl_xor_sync(amask, a1, 1, 4);
            at += __shfl_xor_sync(amask, at, 1, 4);
            a0 += __shfl_xor_sync(amask, a0, 2, 4);
            a1 += __shfl_xor_sync(amask, a1, 2, 4);
            at += __shfl_xor_sync(amask, at, 2, 4);

            s0 = fmaf(C_DT, a0, s0);
            s1 = fmaf(C_DT, a1, s1);
            if (l4 == 0) sh_tq[s][g] = at;
        }
    }
    __syncthreads();

    // ---- torque totals per step ----
    if (tid < C_STEPS) {
        float t0 = 0.f, t1 = 0.f;
        #pragma unroll
        for (int j = 0; j < C_NOSC; j += 2) {
            t0 += sh_tq[tid][j];
            t1 += sh_tq[tid][j + 1];
        }
        sh_torque[tid] = t0 + t1 + sh_direct + fc4_b[0];
    }
    __syncthreads();

    // ---- serial limb integration (thread 0), stage results in smem ----
    if (tid == 0) {
        float th = x0, om = 0.f;
        #pragma unroll 4
        for (int t = 0; t < C_STEPS; ++t) {
            float torque = sh_torque[t];
            float th2 = fmaf(C_DT, om, th);
            float om2 = fmaf(C_DT, torque - C_MGL2 * __sinf(th), om);
            bool hit = (th2 > C_LIM) || (th2 < -C_LIM);
            th2 = fminf(fmaxf(th2, -C_LIM), C_LIM);
            om2 = hit ? 0.f : om2;
            sh_l[2 * t]     = th2;
            sh_l[2 * t + 1] = om2;
            th = th2; om = om2;
        }
    }
    __syncthreads();

    // ---- coalesced output writes ----
    if (tid < 200) out[tid] = sh_l[tid];
    if (tid < 100) out[200 + tid] = sh_torque[tid];
}

extern "C" void kernel_launch(void* const* d_in, const int* in_sizes, int n_in,
                              void* d_out, int out_size) {
    const float* x        = (const float*)d_in[0];
    const float* fc1_w    = (const float*)d_in[1];
    const float* fc1_b    = (const float*)d_in[2];
    const float* fc2_w    = (const float*)d_in[3];
    const float* fc2_b    = (const float*)d_in[4];
    const float* fc3_w    = (const float*)d_in[5];
    const float* fc3_b    = (const float*)d_in[6];
    const float* fcd_w    = (const float*)d_in[7];
    const float* fcd_b    = (const float*)d_in[8];
    const float* fc4_w    = (const float*)d_in[9];
    const float* fc4_b    = (const float*)d_in[10];
    const float* enc      = (const float*)d_in[11];
    const float* osc_bias = (const float*)d_in[12];
    const float* dec      = (const float*)d_in[13];
    float* out = (float*)d_out;

    net_cpg_kernel<<<1, 256>>>(x, fc1_w, fc1_b, fc2_w, fc2_b, fc3_w, fc3_b,
                               fcd_w, fcd_b, fc4_w, fc4_b, enc, osc_bias, dec,
                               out, out_size);
}

// round 4
// speedup vs baseline: 2.5321x; 1.2595x over previous
#include <cuda_runtime.h>
#include <math.h>

#define C_DT    0.01f
#define C_STEPS 100
#define C_NOSC  50
#define C_NPER  50
#define C_LIM   1.0471975511965976f   /* pi/3 */
#define C_MGL2  4.905f                /* m*g*(l/2), I = 1 */
#define NB      25                    /* blocks: 2 oscillators each */

__device__ float g_tq[C_STEPS * 32];  // [step][block], padded row of 32
__device__ float g_direct;

// ============================================================================
// Kernel 1: MLP prologue (redundant per block) + barrier-free 100-step rollout
// ============================================================================
__global__ __launch_bounds__(128, 1)
void cpg_rollout(const float* __restrict__ x,
                 const float* __restrict__ fc1_w, const float* __restrict__ fc1_b,
                 const float* __restrict__ fc2_w, const float* __restrict__ fc2_b,
                 const float* __restrict__ fc3_w, const float* __restrict__ fc3_b,
                 const float* __restrict__ fcd_w, const float* __restrict__ fcd_b,
                 const float* __restrict__ fc4_w, const float* __restrict__ fc4_b,
                 const float* __restrict__ enc,  const float* __restrict__ osc_bias,
                 const float* __restrict__ dec)
{
    __shared__ float sh_h[128];
    __shared__ float sh_h2[128];
    __shared__ float sh_o[4];

    const int tid = threadIdx.x;
    const int bid = blockIdx.x;

    // ---- warp0: per-neuron constants into registers (loads overlap prologue) ----
    float e0[4], e1[4], bb[4], d0[4], d1[4], w4[4];
    if (tid < 32) {
        const int oscl = tid >> 4;           // 0..1
        const int l16  = tid & 15;
        const int osc  = bid * 2 + oscl;     // global oscillator id (< 50)
        #pragma unroll
        for (int k = 0; k < 4; ++k) {
            int n = l16 + 16 * k;
            if (n < C_NPER) {
                int idx = osc * C_NPER + n;
                e0[k] = enc[idx * 2 + 0];
                e1[k] = enc[idx * 2 + 1];
                bb[k] = osc_bias[idx];
                d0[k] = dec[osc * 2 * C_NPER + n];
                d1[k] = dec[osc * 2 * C_NPER + C_NPER + n];
                w4[k] = fc4_w[idx];
            } else {
                e0[k] = e1[k] = bb[k] = d0[k] = d1[k] = w4[k] = 0.f;
            }
        }
    }

    const float x0 = x[0], x1 = x[1];

    // ---- h = relu(fc1 @ x + b1) ----
    {
        float v = fmaf(fc1_w[tid * 2], x0, fmaf(fc1_w[tid * 2 + 1], x1, fc1_b[tid]));
        sh_h[tid] = fmaxf(v, 0.f);
    }
    __syncthreads();

    // ---- h2 = relu(fc2 @ h + b2): one row per thread, float4 loads ----
    {
        const float4* wr = (const float4*)(fc2_w + tid * 128);
        float a0 = 0.f, a1 = 0.f, a2 = 0.f, a3 = 0.f;
        #pragma unroll 8
        for (int j = 0; j < 32; ++j) {
            float4 w = wr[j];
            a0 = fmaf(w.x, sh_h[4 * j + 0], a0);
            a1 = fmaf(w.y, sh_h[4 * j + 1], a1);
            a2 = fmaf(w.z, sh_h[4 * j + 2], a2);
            a3 = fmaf(w.w, sh_h[4 * j + 3], a3);
        }
        sh_h2[tid] = fmaxf((a0 + a1) + (a2 + a3) + fc2_b[tid], 0.f);
    }
    __syncthreads();

    // ---- warp0: direct (block 0 publishes). warp1: this block's 4 fc3 rows. ----
    if (tid < 32) {
        float s = 0.f;
        #pragma unroll
        for (int k = 0; k < 4; ++k)
            s = fmaf(fcd_w[tid + 32 * k], sh_h[tid + 32 * k], s);
        #pragma unroll
        for (int off = 16; off; off >>= 1)
            s += __shfl_down_sync(0xffffffffu, s, off);
        if (tid == 0 && bid == 0) g_direct = s + fcd_b[0] + fc4_b[0];
    } else if (tid < 64) {
        const int r     = (tid - 32) >> 3;       // 0..3
        const int lane8 = tid & 7;
        const int row   = bid * 4 + r;           // global fc3 row (< 100)
        const float* wr = fc3_w + row * 128 + lane8 * 16;
        const float* hv = sh_h2 + lane8 * 16;
        float s = 0.f;
        #pragma unroll
        for (int k = 0; k < 16; ++k) s = fmaf(wr[k], hv[k], s);
        s += __shfl_down_sync(0xffffffffu, s, 4);
        s += __shfl_down_sync(0xffffffffu, s, 2);
        s += __shfl_down_sync(0xffffffffu, s, 1);
        if (lane8 == 0) sh_o[r] = s + fc3_b[row];
    }
    __syncthreads();

    // ---- warp0: 100-step recurrence, 2 oscillators x 16 lanes. No barriers. ----
    if (tid < 32) {
        const int oscl = tid >> 4;
        float s0 = sh_o[oscl * 2];
        float s1 = sh_o[oscl * 2 + 1];

        for (int s = 0; s < C_STEPS; ++s) {
            float a0 = 0.f, a1 = 0.f, at = 0.f;
            #pragma unroll
            for (int k = 0; k < 4; ++k) {
                float a = fmaxf(fmaf(e0[k], s0, fmaf(e1[k], s1, bb[k])), 0.f);
                a0 = fmaf(d0[k], a, a0);
                a1 = fmaf(d1[k], a, a1);
                at = fmaf(w4[k], a, at);
            }
            #pragma unroll
            for (int off = 1; off < 16; off <<= 1) {
                a0 += __shfl_xor_sync(0xffffffffu, a0, off, 16);
                a1 += __shfl_xor_sync(0xffffffffu, a1, off, 16);
                at += __shfl_xor_sync(0xffffffffu, at, off, 16);
            }
            s0 = fmaf(C_DT, a0, s0);
            s1 = fmaf(C_DT, a1, s1);
            // cross-oscillator combine + global store: off the recurrence path
            at += __shfl_xor_sync(0xffffffffu, at, 16);
            if (tid == 0) g_tq[s * 32 + bid] = at;
        }
    }
}

// ============================================================================
// Kernel 2: torque reduction + serial limb integration + output
// ============================================================================
__global__ __launch_bounds__(128, 1)
void cpg_epilogue(const float* __restrict__ x, float* __restrict__ out)
{
    __shared__ float sh_torque[C_STEPS];
    __shared__ float sh_l[2 * C_STEPS];

    const int tid = threadIdx.x;

    if (tid < C_STEPS) {
        float t = 0.f;
        #pragma unroll
        for (int b = 0; b < NB; ++b) t += g_tq[tid * 32 + b];
        sh_torque[tid] = t + g_direct;
    }
    __syncthreads();

    if (tid == 0) {
        float th = x[0], om = 0.f;
        #pragma unroll 4
        for (int t = 0; t < C_STEPS; ++t) {
            float torque = sh_torque[t];
            float th2 = fmaf(C_DT, om, th);
            float om2 = fmaf(C_DT, torque - C_MGL2 * __sinf(th), om);
            bool hit = (th2 > C_LIM) || (th2 < -C_LIM);
            th2 = fminf(fmaxf(th2, -C_LIM), C_LIM);
            om2 = hit ? 0.f : om2;
            sh_l[2 * t]     = th2;
            sh_l[2 * t + 1] = om2;
            th = th2; om = om2;
        }
    }
    __syncthreads();

    // guarded, race-free coalesced writes: out[0..199]=l_states, out[200..299]=torques
    out[tid] = sh_l[tid];                               // 0..127
    if (tid < 72)  out[128 + tid] = sh_l[128 + tid];    // 128..199
    if (tid < 100) out[200 + tid] = sh_torque[tid];     // 200..299
}

extern "C" void kernel_launch(void* const* d_in, const int* in_sizes, int n_in,
                              void* d_out, int out_size) {
    const float* x        = (const float*)d_in[0];
    const float* fc1_w    = (const float*)d_in[1];
    const float* fc1_b    = (const float*)d_in[2];
    const float* fc2_w    = (const float*)d_in[3];
    const float* fc2_b    = (const float*)d_in[4];
    const float* fc3_w    = (const float*)d_in[5];
    const float* fc3_b    = (const float*)d_in[6];
    const float* fcd_w    = (const float*)d_in[7];
    const float* fcd_b    = (const float*)d_in[8];
    const float* fc4_w    = (const float*)d_in[9];
    const float* fc4_b    = (const float*)d_in[10];
    const float* enc      = (const float*)d_in[11];
    const float* osc_bias = (const float*)d_in[12];
    const float* dec      = (const float*)d_in[13];
    float* out = (float*)d_out;

    cpg_rollout<<<NB, 128>>>(x, fc1_w, fc1_b, fc2_w, fc2_b, fc3_w, fc3_b,
                             fcd_w, fcd_b, fc4_w, fc4_b, enc, osc_bias, dec);
    cpg_epilogue<<<1, 128>>>(x, out);
}